// round 9
// baseline (speedup 1.0000x reference)
#include <cuda_runtime.h>
#include <cstdint>

using ull = unsigned long long;

// ---------------- packed f32x2 helpers (FFMA2 via PTX) ----------------
__device__ __forceinline__ void fma2(ull& d, ull a, ull b) {
    asm("fma.rn.f32x2 %0, %1, %2, %0;" : "+l"(d) : "l"(a), "l"(b));
}
__device__ __forceinline__ void unpack2(ull v, float& lo, float& hi) {
    uint32_t l, h;
    asm("mov.b64 {%0, %1}, %2;" : "=r"(l), "=r"(h) : "l"(v));
    lo = __uint_as_float(l); hi = __uint_as_float(h);
}

// ---------------- problem dims ----------------
constexpr int B = 4;
constexpr int D1 = 24, H1 = 301, W1 = 301;               // pooled input, CIN=1
constexpr int C1 = 16, D1o = 11, H1o = 144, W1o = 144;   // conv1 out
constexpr int C2 = 32, D2o = 5,  H2o = 65,  W2o = 65;    // conv2 out
constexpr int C3 = 16, D3o = 2,  H3o = 26,  W3o = 26;    // conv3 out
constexpr int F1V  = C3 * D3o * H3o * W3o;               // 21632
constexpr int TST  = 30;
constexpr int NSNN = B * F1V;                            // 86528
constexpr int N2   = B * C2 * D2o * H2o * W2o;           // 2,704,000
constexpr int C2CH = 8,  C2RC = 6;                       // conv2 split-K: 8 chunks x 6
constexpr int C3CH = 96, C3RC = 1;                       // conv3 split-K: 96 chunks x 1
constexpr int GKC = 52, GKCH = 416, GKB = 8;             // fc1 GEMM split-K

// ---------------- scratch ----------------
__device__ float g_xp[B * D1 * H1 * W1];
__device__ float g_h1[B * C1 * D1o * H1o * W1o];
__device__ float g_p2[C2CH * N2];
__device__ float g_h2[N2];
__device__ float g_p3[C3CH * NSNN];
__device__ float g_xs[NSNN];
__device__ float g_S[TST * NSNN];
__device__ float g_Pp[GKC * TST * B * 512];
__device__ float g_P[TST * B * 512];
__device__ float g_C[B * 512];
__device__ uint32_t g_keys[2 * TST];

// ---------------- avgpool 2x2 ----------------
__global__ void avgpool_k(const float* __restrict__ x) {
    int i = blockIdx.x * blockDim.x + threadIdx.x;
    constexpr int NP = B * D1 * H1 * W1;
    if (i >= NP) return;
    int bc = i / (H1 * W1);
    int s  = i - bc * (H1 * W1);
    int y  = s / W1, xo = s - y * W1;
    const float* p = x + (size_t)bc * 602 * 602 + (size_t)(2 * y) * 602 + 2 * xo;
    g_xp[i] = 0.25f * ((p[0] + p[1]) + (p[602] + p[603]));
}

// ---------------- JAX Threefry-2x32 (partitionable) ----------------
__device__ __forceinline__ uint32_t rotl32(uint32_t x, int d) { return (x << d) | (x >> (32 - d)); }
__device__ __forceinline__ void tfr(uint32_t& x0, uint32_t& x1, int r) { x0 += x1; x1 = rotl32(x1, r); x1 ^= x0; }
__device__ __forceinline__ void threefry2x32(uint32_t k0, uint32_t k1, uint32_t& x0, uint32_t& x1) {
    uint32_t k2 = k0 ^ k1 ^ 0x1BD11BDAu;
    x0 += k0; x1 += k1;
    tfr(x0, x1, 13); tfr(x0, x1, 15); tfr(x0, x1, 26); tfr(x0, x1, 6);
    x0 += k1; x1 += k2 + 1u;
    tfr(x0, x1, 17); tfr(x0, x1, 29); tfr(x0, x1, 16); tfr(x0, x1, 24);
    x0 += k2; x1 += k0 + 2u;
    tfr(x0, x1, 13); tfr(x0, x1, 15); tfr(x0, x1, 26); tfr(x0, x1, 6);
    x0 += k0; x1 += k1 + 3u;
    tfr(x0, x1, 17); tfr(x0, x1, 29); tfr(x0, x1, 16); tfr(x0, x1, 24);
    x0 += k1; x1 += k2 + 4u;
    tfr(x0, x1, 13); tfr(x0, x1, 15); tfr(x0, x1, 26); tfr(x0, x1, 6);
    x0 += k2; x1 += k0 + 5u;
}

// per-step keys (also keeps conv2 in ncu slot #4)
__global__ void key_k() {
    int t = threadIdx.x;
    if (t >= TST) return;
    uint32_t kk0 = 0u, kk1 = (uint32_t)t;
    threefry2x32(0u, 42u, kk0, kk1);
    g_keys[2 * t]     = kk0;
    g_keys[2 * t + 1] = kk1;
}

// ---------------- direct tiled conv3d with FFMA2, duplicated-input smem ----------------
// Input patch stored parity-split as float2(v,v): broadcast-pair = one LDS.64, no MOVs.
// Weights channel-paired, read as LDS.128 over 4 channels (broadcast).
// Per kx per warp: 4 input LDS.64 + NP/2 LDS.128 + 4*NP FFMA2.
template <int CIN, int COUT, int DIN, int HIN, int WIN,
          int DOUT, int HOUT, int WOUT, int TC, int RCPER, bool FUSE,
          int BX, int BZ, int PW>
__global__ void __launch_bounds__(BX * BX * BZ)
conv3d_k(const float* __restrict__ in, const float* __restrict__ wgt,
         const float* __restrict__ bias, float* __restrict__ out) {
    constexpr int PS  = 4 * BX + 13;
    constexpr int OCG = COUT / TC;
    constexpr int NP  = TC / (2 * BZ);
    constexpr int NT  = BX * BX * BZ;
    static_assert(NP % 2 == 0, "NP must be even for LDS.128 weight loads");
    static_assert(PW >= (PS + 1) / 2, "parity plane width too small");

    __shared__ float2 sIn[2][PS][PW];                    // duplicated input
    __shared__ __align__(16) float2 sW2[225][TC / 2];    // channel-pair weights

    const int tiles_x = (WOUT + 2 * BX - 1) / (2 * BX);
    int txt = blockIdx.x % tiles_x, tyt = blockIdx.x / tiles_x;
    int t = blockIdx.y;
    int dout = t % DOUT; t /= DOUT;
    int ocg = t % OCG;
    int chunk = t / OCG;
    int b = blockIdx.z;

    int j = threadIdx.x;
    int i = threadIdx.y;
    int z = (BZ > 1) ? threadIdx.z : 0;
    int tid = (z * BX + i) * BX + j;
    int y0 = tyt * 2 * BX, x0 = txt * 2 * BX;
    int iy0 = 2 * y0, ix0 = 2 * x0;

    ull acc[2][2][NP];
#pragma unroll
    for (int a = 0; a < 2; ++a)
#pragma unroll
        for (int c = 0; c < 2; ++c)
#pragma unroll
            for (int u = 0; u < NP; ++u) acc[a][c][u] = 0ull;

    float* sWf = &sW2[0][0].x;

    const int rc0 = chunk * RCPER;
    for (int rc = rc0; rc < rc0 + RCPER; ++rc) {
        int ci = rc / 3, kd = rc - ci * 3;
        const float* ip = in + (((size_t)b * CIN + ci) * DIN + (2 * dout + kd)) * (size_t)(HIN * WIN);
        const float* wp = wgt + ((size_t)(ocg * TC) * CIN + ci) * 675 + (size_t)kd * 225;

        __syncthreads();
        for (int s = tid; s < PS * PS; s += NT) {
            int r = s / PS, c = s - PS * r;
            int gy = iy0 + r, gx = ix0 + c;
            float v = 0.f;
            if (gy < HIN && gx < WIN) v = ip[(size_t)gy * WIN + gx];
            sIn[c & 1][r][c >> 1] = make_float2(v, v);
        }
        for (int s = tid; s < TC * 225; s += NT) {
            int oc = s / 225, u = s - 225 * oc;
            sWf[u * TC + oc] = wp[(size_t)oc * (CIN * 675) + u];
        }
        __syncthreads();

        for (int ky = 0; ky < 15; ++ky) {
            int r0 = 2 * i + ky;
            const ull* pe0 = reinterpret_cast<const ull*>(sIn[0][r0]);
            const ull* po0 = reinterpret_cast<const ull*>(sIn[1][r0]);
            const ull* pe1 = reinterpret_cast<const ull*>(sIn[0][r0 + 2 * BX]);
            const ull* po1 = reinterpret_cast<const ull*>(sIn[1][r0 + 2 * BX]);
#pragma unroll
            for (int kx = 0; kx < 15; ++kx) {
                const int cb = kx >> 1;
                const ull* q0 = (kx & 1) ? po0 : pe0;
                const ull* q1 = (kx & 1) ? po1 : pe1;
                ull a00 = q0[j + cb];
                ull a01 = q0[j + BX + cb];
                ull a10 = q1[j + cb];
                ull a11 = q1[j + BX + cb];
                const ulonglong2* wr =
                    reinterpret_cast<const ulonglong2*>(&sW2[ky * 15 + kx][z * NP]);
#pragma unroll
                for (int u2 = 0; u2 < NP / 2; ++u2) {
                    ulonglong2 w = wr[u2];
                    fma2(acc[0][0][2 * u2],     a00, w.x);
                    fma2(acc[0][1][2 * u2],     a01, w.x);
                    fma2(acc[1][0][2 * u2],     a10, w.x);
                    fma2(acc[1][1][2 * u2],     a11, w.x);
                    fma2(acc[0][0][2 * u2 + 1], a00, w.y);
                    fma2(acc[0][1][2 * u2 + 1], a01, w.y);
                    fma2(acc[1][0][2 * u2 + 1], a10, w.y);
                    fma2(acc[1][1][2 * u2 + 1], a11, w.y);
                }
            }
        }
    }

    const size_t plane = (size_t)HOUT * WOUT;
#pragma unroll
    for (int a = 0; a < 2; ++a) {
        int oy = y0 + i + a * BX;
        if (oy >= HOUT) continue;
#pragma unroll
        for (int c = 0; c < 2; ++c) {
            int ox = x0 + j + c * BX;
            if (ox >= WOUT) continue;
#pragma unroll
            for (int u = 0; u < NP; ++u) {
                float lo, hi;
                unpack2(acc[a][c][u], lo, hi);
                int oc0 = ocg * TC + z * (2 * NP) + 2 * u;
#pragma unroll
                for (int h = 0; h < 2; ++h) {
                    int oc = oc0 + h;
                    float v = h ? hi : lo;
                    size_t idx = (((size_t)b * COUT + oc) * DOUT + dout) * plane + (size_t)oy * WOUT + ox;
                    if (FUSE) {
                        v += bias[oc];
                        out[idx] = v > 0.f ? v : 0.f;
                    } else {
                        out[(size_t)chunk * ((size_t)B * COUT * DOUT * plane) + idx] = v;
                    }
                }
            }
        }
    }
}

// ---------------- conv2 split-K reduce + bias + relu ----------------
__global__ void c2red_k(const float* __restrict__ b2) {
    int i = blockIdx.x * blockDim.x + threadIdx.x;
    if (i >= N2) return;
    float s = 0.f;
#pragma unroll
    for (int c = 0; c < C2CH; ++c) s += g_p2[(size_t)c * N2 + i];
    int oc = (i / (D2o * H2o * W2o)) % C2;
    s += b2[oc];
    g_h2[i] = s > 0.f ? s : 0.f;
}

// ---------------- conv3 split-K reduce + bias + relu -> x_snn ----------------
__global__ void c3red_k(const float* __restrict__ b3) {
    int i = blockIdx.x * blockDim.x + threadIdx.x;
    if (i >= NSNN) return;
    float s = 0.f;
#pragma unroll 8
    for (int c = 0; c < C3CH; ++c) s += g_p3[(size_t)c * NSNN + i];
    int oc = (i / (D3o * H3o * W3o)) % C3;
    s += b3[oc];
    g_xs[i] = s > 0.f ? s : 0.f;
}

// spikes, using precomputed per-step keys
__global__ void spike_k() {
    int i = blockIdx.x * blockDim.x + threadIdx.x;
    if (i >= TST * NSNN) return;
    int t = i / NSNN;
    int e = i - t * NSNN;
    uint32_t c0 = 0u, c1 = (uint32_t)e;
    threefry2x32(g_keys[2 * t], g_keys[2 * t + 1], c0, c1);
    uint32_t bits = c0 ^ c1;
    float u = __uint_as_float((bits >> 9) | 0x3f800000u) - 1.0f;
    float x = g_xs[e];
    float prob = 0.5f * fabsf(x);
    float sgn = (x > 0.f) ? 1.f : ((x < 0.f) ? -1.f : 0.f);
    g_S[i] = (prob > u) ? sgn : 0.f;
}

// ---------------- GEMM: P[120][512] = S[120][21632] @ fc1_w[512][.]^T (split-K, N-block 64) ----------------
__global__ void __launch_bounds__(256) gemm_k(const float* __restrict__ W) {
    __shared__ float sA[GKB][120];
    __shared__ float sB[GKB][64];
    int tid = threadIdx.x;
    int tx = tid & 31, ty = tid >> 5;
    int nt = blockIdx.x;
    int kc = blockIdx.y;
    int k0 = kc * GKCH;

    float acc[15][2];
#pragma unroll
    for (int r = 0; r < 15; ++r) { acc[r][0] = 0.f; acc[r][1] = 0.f; }

    for (int kk = 0; kk < GKCH; kk += GKB) {
        __syncthreads();
        for (int s = tid; s < 120 * GKB; s += 256) {
            int m = s >> 3, k = s & 7;
            sA[k][m] = g_S[(size_t)m * F1V + k0 + kk + k];
        }
        for (int s = tid; s < 64 * GKB; s += 256) {
            int n = s >> 3, k = s & 7;
            sB[k][n] = W[(size_t)(nt * 64 + n) * F1V + k0 + kk + k];
        }
        __syncthreads();
#pragma unroll
        for (int k = 0; k < GKB; ++k) {
            float bv0 = sB[k][tx];
            float bv1 = sB[k][tx + 32];
#pragma unroll
            for (int r = 0; r < 15; ++r) {
                float av = sA[k][ty + 8 * r];
                acc[r][0] = fmaf(av, bv0, acc[r][0]);
                acc[r][1] = fmaf(av, bv1, acc[r][1]);
            }
        }
    }
#pragma unroll
    for (int r = 0; r < 15; ++r) {
        g_Pp[((size_t)kc * 120 + (ty + 8 * r)) * 512 + nt * 64 + tx]      = acc[r][0];
        g_Pp[((size_t)kc * 120 + (ty + 8 * r)) * 512 + nt * 64 + tx + 32] = acc[r][1];
    }
}

__global__ void reduceP_k() {
    int i = blockIdx.x * blockDim.x + threadIdx.x;
    if (i >= 120 * 512) return;
    float s = 0.f;
    for (int c = 0; c < GKC; ++c) s += g_Pp[(size_t)c * 120 * 512 + i];
    g_P[i] = s;
}

// ---------------- LIF recurrence ----------------
__global__ void snn_k(const float* __restrict__ fc1_b) {
    int i = blockIdx.x * blockDim.x + threadIdx.x;
    if (i >= B * 512) return;
    int b = i >> 9, jj = i & 511;
    float bias = fc1_b[jj];
    float m0 = 0.f, cnt = 0.f;
#pragma unroll
    for (int t = 0; t < TST; ++t) {
        m0 += g_P[((t * B) + b) * 512 + jj] + bias;
        if (m0 > 1.0f) { cnt += 1.f; m0 = 0.f; }
    }
    g_C[i] = cnt;
}

// ---------------- final fc2 ----------------
__global__ void fc2_k(const float* __restrict__ W2, const float* __restrict__ b2f,
                      float* __restrict__ out) {
    int o = blockIdx.x, b = blockIdx.y;
    int tid = threadIdx.x;
    float s = 0.f;
    for (int jj = tid; jj < 512; jj += 128) s += g_C[b * 512 + jj] * W2[o * 512 + jj];
    __shared__ float red[128];
    red[tid] = s;
    __syncthreads();
    for (int w = 64; w > 0; w >>= 1) { if (tid < w) red[tid] += red[tid + w]; __syncthreads(); }
    if (tid == 0) out[b * 54 + o] = red[0] + 30.0f * b2f[o];
}

// ---------------- launch ----------------
extern "C" void kernel_launch(void* const* d_in, const int* in_sizes, int n_in,
                              void* d_out, int out_size) {
    const float* x    = (const float*)d_in[0];
    const float* w1   = (const float*)d_in[1];
    const float* b1   = (const float*)d_in[2];
    const float* w2   = (const float*)d_in[3];
    const float* b2   = (const float*)d_in[4];
    const float* w3   = (const float*)d_in[5];
    const float* b3   = (const float*)d_in[6];
    const float* fc1w = (const float*)d_in[7];
    const float* fc1b = (const float*)d_in[8];
    const float* fc2w = (const float*)d_in[9];
    const float* fc2b = (const float*)d_in[10];
    float* out = (float*)d_out;

    float *p_xp, *p_h1, *p_h2, *p_p2, *p_p3;
    cudaGetSymbolAddress((void**)&p_xp, g_xp);
    cudaGetSymbolAddress((void**)&p_h1, g_h1);
    cudaGetSymbolAddress((void**)&p_h2, g_h2);
    cudaGetSymbolAddress((void**)&p_p2, g_p2);
    cudaGetSymbolAddress((void**)&p_p3, g_p3);

    constexpr int NPOOL = B * D1 * H1 * W1;
    avgpool_k<<<(NPOOL + 255) / 256, 256>>>(x);                       // #1

    // conv1: tile 24x24 exact, block (12,12,1), TC=16, dup-input PW=31 (44.7KB smem)
    conv3d_k<1, 16, 24, 301, 301, 11, 144, 144, 16, 3, true, 12, 1, 31>
        <<<dim3(36, 11, 4), dim3(12, 12, 1)>>>(p_xp, w1, b1, p_h1);   // #2

    key_k<<<1, 32>>>();                                               // #3

    // conv2: tile 22x22, block (11,11,1), TC=16 (OCG=2), split-K 8x6, dup-input PW=29 (40.8KB)
    conv3d_k<16, 32, 11, 144, 144, 5, 65, 65, 16, C2RC, false, 11, 1, 29>
        <<<dim3(9, 80, 4), dim3(11, 11, 1)>>>(p_h1, w2, nullptr, p_p2);   // #4 <- profiled
    c2red_k<<<(N2 + 255) / 256, 256>>>(b2);                           // #5

    // conv3: tile 26x26 exact, block (13,13,1), TC=8 (OCG=2), split-K 96x1, PW=33 (41.5KB)
    // grid.y = 2 * 2 * 96 = 384
    conv3d_k<32, 16, 5, 65, 65, 2, 26, 26, 8, C3RC, false, 13, 1, 33>
        <<<dim3(1, 384, 4), dim3(13, 13, 1)>>>(p_h2, w3, nullptr, p_p3);  // #6
    c3red_k<<<(NSNN + 255) / 256, 256>>>(b3);                         // #7

    spike_k<<<(TST * NSNN + 255) / 256, 256>>>();                     // #8
    gemm_k<<<dim3(8, GKC), 256>>>(fc1w);                              // #9
    reduceP_k<<<(120 * 512 + 255) / 256, 256>>>();                    // #10
    snn_k<<<8, 256>>>(fc1b);                                          // #11
    fc2_k<<<dim3(54, 4), 128>>>(fc2w, fc2b, out);                     // #12
}

// round 10
// speedup vs baseline: 1.1450x; 1.1450x over previous
#include <cuda_runtime.h>
#include <cstdint>

using ull = unsigned long long;

// ---------------- packed f32x2 helpers (FFMA2 via PTX) ----------------
__device__ __forceinline__ ull pack2(float v) {
    ull r;
    asm("mov.b64 %0, {%1, %1};" : "=l"(r) : "r"(__float_as_uint(v)));
    return r;
}
__device__ __forceinline__ void fma2(ull& d, ull a, ull b) {
    asm("fma.rn.f32x2 %0, %1, %2, %0;" : "+l"(d) : "l"(a), "l"(b));
}
__device__ __forceinline__ void unpack2(ull v, float& lo, float& hi) {
    uint32_t l, h;
    asm("mov.b64 {%0, %1}, %2;" : "=r"(l), "=r"(h) : "l"(v));
    lo = __uint_as_float(l); hi = __uint_as_float(h);
}

// ---------------- problem dims ----------------
constexpr int B = 4;
constexpr int D1 = 24, H1 = 301, W1 = 301;               // pooled input, CIN=1
constexpr int C1 = 16, D1o = 11, H1o = 144, W1o = 144;   // conv1 out
constexpr int C2 = 32, D2o = 5,  H2o = 65,  W2o = 65;    // conv2 out
constexpr int C3 = 16, D3o = 2,  H3o = 26,  W3o = 26;    // conv3 out
constexpr int F1V  = C3 * D3o * H3o * W3o;               // 21632
constexpr int TST  = 30;
constexpr int NSNN = B * F1V;                            // 86528
constexpr int N2   = B * C2 * D2o * H2o * W2o;           // 2,704,000
constexpr int C2CH = 8,  C2RC = 6;                       // conv2 split-K: 8 chunks x 6
constexpr int C3CH = 96, C3RC = 1;                       // conv3 split-K: 96 chunks x 1
constexpr int GKC = 52, GKCH = 416, GKB = 8;             // fc1 GEMM split-K

// ---------------- scratch ----------------
__device__ float g_xp[B * D1 * H1 * W1];
__device__ float g_h1[B * C1 * D1o * H1o * W1o];
__device__ float g_p2[C2CH * N2];
__device__ float g_h2[N2];
__device__ float g_p3[C3CH * NSNN];
__device__ float g_xs[NSNN];
__device__ float g_S[TST * NSNN];
__device__ float g_Pp[GKC * TST * B * 512];
__device__ float g_P[TST * B * 512];
__device__ float g_C[B * 512];
__device__ uint32_t g_keys[2 * TST];

// ---------------- avgpool 2x2 ----------------
__global__ void avgpool_k(const float* __restrict__ x) {
    int i = blockIdx.x * blockDim.x + threadIdx.x;
    constexpr int NP = B * D1 * H1 * W1;
    if (i >= NP) return;
    int bc = i / (H1 * W1);
    int s  = i - bc * (H1 * W1);
    int y  = s / W1, xo = s - y * W1;
    const float* p = x + (size_t)bc * 602 * 602 + (size_t)(2 * y) * 602 + 2 * xo;
    g_xp[i] = 0.25f * ((p[0] + p[1]) + (p[602] + p[603]));
}

// ---------------- JAX Threefry-2x32 (partitionable) ----------------
__device__ __forceinline__ uint32_t rotl32(uint32_t x, int d) { return (x << d) | (x >> (32 - d)); }
__device__ __forceinline__ void tfr(uint32_t& x0, uint32_t& x1, int r) { x0 += x1; x1 = rotl32(x1, r); x1 ^= x0; }
__device__ __forceinline__ void threefry2x32(uint32_t k0, uint32_t k1, uint32_t& x0, uint32_t& x1) {
    uint32_t k2 = k0 ^ k1 ^ 0x1BD11BDAu;
    x0 += k0; x1 += k1;
    tfr(x0, x1, 13); tfr(x0, x1, 15); tfr(x0, x1, 26); tfr(x0, x1, 6);
    x0 += k1; x1 += k2 + 1u;
    tfr(x0, x1, 17); tfr(x0, x1, 29); tfr(x0, x1, 16); tfr(x0, x1, 24);
    x0 += k2; x1 += k0 + 2u;
    tfr(x0, x1, 13); tfr(x0, x1, 15); tfr(x0, x1, 26); tfr(x0, x1, 6);
    x0 += k0; x1 += k1 + 3u;
    tfr(x0, x1, 17); tfr(x0, x1, 29); tfr(x0, x1, 16); tfr(x0, x1, 24);
    x0 += k1; x1 += k2 + 4u;
    tfr(x0, x1, 13); tfr(x0, x1, 15); tfr(x0, x1, 26); tfr(x0, x1, 6);
    x0 += k2; x1 += k0 + 5u;
}

// per-step keys (also keeps conv2 in ncu slot #4)
__global__ void key_k() {
    int t = threadIdx.x;
    if (t >= TST) return;
    uint32_t kk0 = 0u, kk1 = (uint32_t)t;
    threefry2x32(0u, 42u, kk0, kk1);
    g_keys[2 * t]     = kk0;
    g_keys[2 * t + 1] = kk1;
}

// ---------------- direct tiled conv3d with FFMA2 ----------------
// Scalar input LDS (parity-split) + pack2; weights as LDS.128 over 4 adjacent channels.
// MINB forces extra resident blocks (reg cap ~102-113) to fix eligible-warp starvation.
template <int CIN, int COUT, int DIN, int HIN, int WIN,
          int DOUT, int HOUT, int WOUT, int TC, int RCPER, bool FUSE,
          int BX, int BZ, int PW, int MINB>
__global__ void __launch_bounds__(BX * BX * BZ, MINB)
conv3d_k(const float* __restrict__ in, const float* __restrict__ wgt,
         const float* __restrict__ bias, float* __restrict__ out) {
    constexpr int PS  = 4 * BX + 13;
    constexpr int OCG = COUT / TC;
    constexpr int NP  = TC / (2 * BZ);
    constexpr int NT  = BX * BX * BZ;
    static_assert(NP % 2 == 0, "NP must be even for LDS.128 weight loads");

    __shared__ float sIn[2][PS][PW];
    __shared__ __align__(16) float2 sW2[225][TC / 2];

    const int tiles_x = (WOUT + 2 * BX - 1) / (2 * BX);
    int txt = blockIdx.x % tiles_x, tyt = blockIdx.x / tiles_x;
    int t = blockIdx.y;
    int dout = t % DOUT; t /= DOUT;
    int ocg = t % OCG;
    int chunk = t / OCG;
    int b = blockIdx.z;

    int j = threadIdx.x;
    int i = threadIdx.y;
    int z = (BZ > 1) ? threadIdx.z : 0;
    int tid = (z * BX + i) * BX + j;
    int y0 = tyt * 2 * BX, x0 = txt * 2 * BX;
    int iy0 = 2 * y0, ix0 = 2 * x0;

    ull acc[2][2][NP];
#pragma unroll
    for (int a = 0; a < 2; ++a)
#pragma unroll
        for (int c = 0; c < 2; ++c)
#pragma unroll
            for (int u = 0; u < NP; ++u) acc[a][c][u] = 0ull;

    float* sWf = &sW2[0][0].x;

    const int rc0 = chunk * RCPER;
    for (int rc = rc0; rc < rc0 + RCPER; ++rc) {
        int ci = rc / 3, kd = rc - ci * 3;
        const float* ip = in + (((size_t)b * CIN + ci) * DIN + (2 * dout + kd)) * (size_t)(HIN * WIN);
        const float* wp = wgt + ((size_t)(ocg * TC) * CIN + ci) * 675 + (size_t)kd * 225;

        __syncthreads();
        for (int s = tid; s < PS * PS; s += NT) {
            int r = s / PS, c = s - PS * r;
            int gy = iy0 + r, gx = ix0 + c;
            float v = 0.f;
            if (gy < HIN && gx < WIN) v = ip[(size_t)gy * WIN + gx];
            sIn[c & 1][r][c >> 1] = v;
        }
        for (int s = tid; s < TC * 225; s += NT) {
            int oc = s / 225, u = s - 225 * oc;
            sWf[u * TC + oc] = wp[(size_t)oc * (CIN * 675) + u];
        }
        __syncthreads();

        for (int ky = 0; ky < 15; ++ky) {
            int r0 = 2 * i + ky;
            const float* pe0 = sIn[0][r0];
            const float* po0 = sIn[1][r0];
            const float* pe1 = sIn[0][r0 + 2 * BX];
            const float* po1 = sIn[1][r0 + 2 * BX];
#pragma unroll
            for (int kx = 0; kx < 15; ++kx) {
                const int cb = kx >> 1;
                const float* q0 = (kx & 1) ? po0 : pe0;
                const float* q1 = (kx & 1) ? po1 : pe1;
                ull a00 = pack2(q0[j + cb]);
                ull a01 = pack2(q0[j + BX + cb]);
                ull a10 = pack2(q1[j + cb]);
                ull a11 = pack2(q1[j + BX + cb]);
                const ulonglong2* wr =
                    reinterpret_cast<const ulonglong2*>(&sW2[ky * 15 + kx][z * NP]);
#pragma unroll
                for (int u2 = 0; u2 < NP / 2; ++u2) {
                    ulonglong2 w = wr[u2];
                    fma2(acc[0][0][2 * u2],     a00, w.x);
                    fma2(acc[0][1][2 * u2],     a01, w.x);
                    fma2(acc[1][0][2 * u2],     a10, w.x);
                    fma2(acc[1][1][2 * u2],     a11, w.x);
                    fma2(acc[0][0][2 * u2 + 1], a00, w.y);
                    fma2(acc[0][1][2 * u2 + 1], a01, w.y);
                    fma2(acc[1][0][2 * u2 + 1], a10, w.y);
                    fma2(acc[1][1][2 * u2 + 1], a11, w.y);
                }
            }
        }
    }

    const size_t plane = (size_t)HOUT * WOUT;
#pragma unroll
    for (int a = 0; a < 2; ++a) {
        int oy = y0 + i + a * BX;
        if (oy >= HOUT) continue;
#pragma unroll
        for (int c = 0; c < 2; ++c) {
            int ox = x0 + j + c * BX;
            if (ox >= WOUT) continue;
#pragma unroll
            for (int u = 0; u < NP; ++u) {
                float lo, hi;
                unpack2(acc[a][c][u], lo, hi);
                int oc0 = ocg * TC + z * (2 * NP) + 2 * u;
#pragma unroll
                for (int h = 0; h < 2; ++h) {
                    int oc = oc0 + h;
                    float v = h ? hi : lo;
                    size_t idx = (((size_t)b * COUT + oc) * DOUT + dout) * plane + (size_t)oy * WOUT + ox;
                    if (FUSE) {
                        v += bias[oc];
                        out[idx] = v > 0.f ? v : 0.f;
                    } else {
                        out[(size_t)chunk * ((size_t)B * COUT * DOUT * plane) + idx] = v;
                    }
                }
            }
        }
    }
}

// ---------------- conv2 split-K reduce + bias + relu ----------------
__global__ void c2red_k(const float* __restrict__ b2) {
    int i = blockIdx.x * blockDim.x + threadIdx.x;
    if (i >= N2) return;
    float s = 0.f;
#pragma unroll
    for (int c = 0; c < C2CH; ++c) s += g_p2[(size_t)c * N2 + i];
    int oc = (i / (D2o * H2o * W2o)) % C2;
    s += b2[oc];
    g_h2[i] = s > 0.f ? s : 0.f;
}

// ---------------- conv3 split-K reduce + bias + relu -> x_snn ----------------
__global__ void c3red_k(const float* __restrict__ b3) {
    int i = blockIdx.x * blockDim.x + threadIdx.x;
    if (i >= NSNN) return;
    float s = 0.f;
#pragma unroll 8
    for (int c = 0; c < C3CH; ++c) s += g_p3[(size_t)c * NSNN + i];
    int oc = (i / (D3o * H3o * W3o)) % C3;
    s += b3[oc];
    g_xs[i] = s > 0.f ? s : 0.f;
}

// spikes, using precomputed per-step keys
__global__ void spike_k() {
    int i = blockIdx.x * blockDim.x + threadIdx.x;
    if (i >= TST * NSNN) return;
    int t = i / NSNN;
    int e = i - t * NSNN;
    uint32_t c0 = 0u, c1 = (uint32_t)e;
    threefry2x32(g_keys[2 * t], g_keys[2 * t + 1], c0, c1);
    uint32_t bits = c0 ^ c1;
    float u = __uint_as_float((bits >> 9) | 0x3f800000u) - 1.0f;
    float x = g_xs[e];
    float prob = 0.5f * fabsf(x);
    float sgn = (x > 0.f) ? 1.f : ((x < 0.f) ? -1.f : 0.f);
    g_S[i] = (prob > u) ? sgn : 0.f;
}

// ---------------- GEMM: P[120][512] = S[120][21632] @ fc1_w[512][.]^T (split-K, N-block 64) ----------------
__global__ void __launch_bounds__(256) gemm_k(const float* __restrict__ W) {
    __shared__ float sA[GKB][120];
    __shared__ float sB[GKB][64];
    int tid = threadIdx.x;
    int tx = tid & 31, ty = tid >> 5;
    int nt = blockIdx.x;
    int kc = blockIdx.y;
    int k0 = kc * GKCH;

    float acc[15][2];
#pragma unroll
    for (int r = 0; r < 15; ++r) { acc[r][0] = 0.f; acc[r][1] = 0.f; }

    for (int kk = 0; kk < GKCH; kk += GKB) {
        __syncthreads();
        for (int s = tid; s < 120 * GKB; s += 256) {
            int m = s >> 3, k = s & 7;
            sA[k][m] = g_S[(size_t)m * F1V + k0 + kk + k];
        }
        for (int s = tid; s < 64 * GKB; s += 256) {
            int n = s >> 3, k = s & 7;
            sB[k][n] = W[(size_t)(nt * 64 + n) * F1V + k0 + kk + k];
        }
        __syncthreads();
#pragma unroll
        for (int k = 0; k < GKB; ++k) {
            float bv0 = sB[k][tx];
            float bv1 = sB[k][tx + 32];
#pragma unroll
            for (int r = 0; r < 15; ++r) {
                float av = sA[k][ty + 8 * r];
                acc[r][0] = fmaf(av, bv0, acc[r][0]);
                acc[r][1] = fmaf(av, bv1, acc[r][1]);
            }
        }
    }
#pragma unroll
    for (int r = 0; r < 15; ++r) {
        g_Pp[((size_t)kc * 120 + (ty + 8 * r)) * 512 + nt * 64 + tx]      = acc[r][0];
        g_Pp[((size_t)kc * 120 + (ty + 8 * r)) * 512 + nt * 64 + tx + 32] = acc[r][1];
    }
}

__global__ void reduceP_k() {
    int i = blockIdx.x * blockDim.x + threadIdx.x;
    if (i >= 120 * 512) return;
    float s = 0.f;
    for (int c = 0; c < GKC; ++c) s += g_Pp[(size_t)c * 120 * 512 + i];
    g_P[i] = s;
}

// ---------------- LIF recurrence ----------------
__global__ void snn_k(const float* __restrict__ fc1_b) {
    int i = blockIdx.x * blockDim.x + threadIdx.x;
    if (i >= B * 512) return;
    int b = i >> 9, jj = i & 511;
    float bias = fc1_b[jj];
    float m0 = 0.f, cnt = 0.f;
#pragma unroll
    for (int t = 0; t < TST; ++t) {
        m0 += g_P[((t * B) + b) * 512 + jj] + bias;
        if (m0 > 1.0f) { cnt += 1.f; m0 = 0.f; }
    }
    g_C[i] = cnt;
}

// ---------------- final fc2 ----------------
__global__ void fc2_k(const float* __restrict__ W2, const float* __restrict__ b2f,
                      float* __restrict__ out) {
    int o = blockIdx.x, b = blockIdx.y;
    int tid = threadIdx.x;
    float s = 0.f;
    for (int jj = tid; jj < 512; jj += 128) s += g_C[b * 512 + jj] * W2[o * 512 + jj];
    __shared__ float red[128];
    red[tid] = s;
    __syncthreads();
    for (int w = 64; w > 0; w >>= 1) { if (tid < w) red[tid] += red[tid + w]; __syncthreads(); }
    if (tid == 0) out[b * 54 + o] = red[0] + 30.0f * b2f[o];
}

// ---------------- launch ----------------
extern "C" void kernel_launch(void* const* d_in, const int* in_sizes, int n_in,
                              void* d_out, int out_size) {
    const float* x    = (const float*)d_in[0];
    const float* w1   = (const float*)d_in[1];
    const float* b1   = (const float*)d_in[2];
    const float* w2   = (const float*)d_in[3];
    const float* b2   = (const float*)d_in[4];
    const float* w3   = (const float*)d_in[5];
    const float* b3   = (const float*)d_in[6];
    const float* fc1w = (const float*)d_in[7];
    const float* fc1b = (const float*)d_in[8];
    const float* fc2w = (const float*)d_in[9];
    const float* fc2b = (const float*)d_in[10];
    float* out = (float*)d_out;

    float *p_xp, *p_h1, *p_h2, *p_p2, *p_p3;
    cudaGetSymbolAddress((void**)&p_xp, g_xp);
    cudaGetSymbolAddress((void**)&p_h1, g_h1);
    cudaGetSymbolAddress((void**)&p_h2, g_h2);
    cudaGetSymbolAddress((void**)&p_p2, g_p2);
    cudaGetSymbolAddress((void**)&p_p3, g_p3);

    constexpr int NPOOL = B * D1 * H1 * W1;
    avgpool_k<<<(NPOOL + 255) / 256, 256>>>(x);                       // #1

    // conv1: tile 24x24 exact, block (12,12,1), TC=16, MINB=4 (reg cap ~102)
    conv3d_k<1, 16, 24, 301, 301, 11, 144, 144, 16, 3, true, 12, 1, 38, 4>
        <<<dim3(36, 11, 4), dim3(12, 12, 1)>>>(p_xp, w1, b1, p_h1);   // #2

    key_k<<<1, 32>>>();                                               // #3

    // conv2: tile 22x22, block (11,11,1), TC=16 (OCG=2), split-K 8x6, MINB=5 (reg cap ~102)
    conv3d_k<16, 32, 11, 144, 144, 5, 65, 65, 16, C2RC, false, 11, 1, 38, 5>
        <<<dim3(9, 80, 4), dim3(11, 11, 1)>>>(p_h1, w2, nullptr, p_p2);   // #4 <- profiled
    c2red_k<<<(N2 + 255) / 256, 256>>>(b2);                           // #5

    // conv3: tile 26x26 exact, block (13,13,1), TC=16 (OCG=1), split-K 96x1, MINB=3 (reg cap ~113)
    conv3d_k<32, 16, 5, 65, 65, 2, 26, 26, 16, C3RC, false, 13, 1, 38, 3>
        <<<dim3(1, 192, 4), dim3(13, 13, 1)>>>(p_h2, w3, nullptr, p_p3);  // #6
    c3red_k<<<(NSNN + 255) / 256, 256>>>(b3);                         // #7

    spike_k<<<(TST * NSNN + 255) / 256, 256>>>();                     // #8
    gemm_k<<<dim3(8, GKC), 256>>>(fc1w);                              // #9
    reduceP_k<<<(120 * 512 + 255) / 256, 256>>>();                    // #10
    snn_k<<<8, 256>>>(fc1b);                                          // #11
    fc2_k<<<dim3(54, 4), 128>>>(fc2w, fc2b, out);                     // #12
}